// round 13
// baseline (speedup 1.0000x reference)
#include <cuda_runtime.h>
#include <cuda_bf16.h>
#include <cstdint>

typedef unsigned long long u64;

// Cross-block scratch (no allocations allowed -> __device__ globals)
__device__ float2 g_v[4][4096];       // 4 columns of the circuit unitary
__device__ u64 g_sX[2][4][2048];      // double-buffered per-column staging, X
__device__ u64 g_sY[2][4][2048];      // double-buffered per-column staging, Y
__device__ unsigned g_flag = 0;       // sim-done counter (target 8)
__device__ int g_done2 = 0;           // output-blocks-passed-spin counter

// ---------------- f32x2 packed helpers ----------------
__device__ __forceinline__ u64 pack2(float x, float y) {
    u64 u; asm("mov.b64 %0, {%1,%2};" : "=l"(u) : "f"(x), "f"(y)); return u;
}
__device__ __forceinline__ float2 unpack2(u64 u) {
    float2 v; asm("mov.b64 {%0,%1}, %2;" : "=f"(v.x), "=f"(v.y) : "l"(u)); return v;
}
__device__ __forceinline__ u64 swap2(u64 u) {
    float2 v = unpack2(u); return pack2(v.y, v.x);
}
__device__ __forceinline__ u64 fma2(u64 a, u64 b, u64 c) {
    u64 d; asm("fma.rn.f32x2 %0, %1, %2, %3;" : "=l"(d) : "l"(a), "l"(b), "l"(c)); return d;
}
__device__ __forceinline__ u64 mul2(u64 a, u64 b) {
    u64 d; asm("mul.rn.f32x2 %0, %1, %2;" : "=l"(d) : "l"(a), "l"(b)); return d;
}
__device__ __forceinline__ float ldcg(const float* p) {
    float v; asm volatile("ld.global.cg.f32 %0, [%1];" : "=f"(v) : "l"(p)); return v;
}
__device__ __forceinline__ void stcg64(u64* p, u64 v) {
    asm volatile("st.global.cg.b64 [%0], %1;" :: "l"(p), "l"(v));
}
__device__ __forceinline__ void red_release_add(unsigned* p, unsigned v) {
    asm volatile("red.release.gpu.global.add.u32 [%0], %1;" :: "l"(p), "r"(v) : "memory");
}
__device__ __forceinline__ unsigned ld_acquire(const unsigned* p) {
    unsigned v;
    asm volatile("ld.acquire.gpu.global.u32 %0, [%1];" : "=r"(v) : "l"(p) : "memory");
    return v;
}

// ---------------- cluster / mbarrier helpers ----------------
__device__ __forceinline__ uint32_t smem32(const void* p) {
    uint32_t a;
    asm("{ .reg .u64 t; cvta.to.shared.u64 t, %1; cvt.u32.u64 %0, t; }"
        : "=r"(a) : "l"(p));
    return a;
}
__device__ __forceinline__ void mbar_init(uint32_t a, unsigned cnt) {
    asm volatile("mbarrier.init.shared.b64 [%0], %1;" :: "r"(a), "r"(cnt) : "memory");
}
__device__ __forceinline__ void mbar_arrive_peer(uint32_t a, unsigned peer) {
    asm volatile(
        "{\n\t.reg .b32 ra;\n\t"
        "mapa.shared::cluster.u32 ra, %0, %1;\n\t"
        "mbarrier.arrive.release.cluster.shared::cluster.b64 _, [ra];\n\t}"
        :: "r"(a), "r"(peer) : "memory");
}
__device__ __forceinline__ void mbar_wait(uint32_t a, unsigned parity) {
    asm volatile(
        "{\n\t.reg .pred P;\n\t"
        "W%=:\n\t"
        "mbarrier.try_wait.parity.acquire.cluster.shared::cta.b64 P, [%0], %1;\n\t"
        "@P bra.uni D%=;\n\t"
        "bra.uni W%=;\n\t"
        "D%=:\n\t}"
        :: "r"(a), "r"(parity) : "memory");
}
#define CLUSTER_ARRIVE() asm volatile("barrier.cluster.arrive.aligned;" ::: "memory")
#define CLUSTER_WAIT()   asm volatile("barrier.cluster.wait.aligned;" ::: "memory")

struct Coef { u64 sx, sy, nsy, ox, oy, noy; };

// 16B-aligned blocks (stride 144B per gate, sub-blocks at +0/+48/+96) -> LDS.128
__device__ __forceinline__ Coef ldCoef(const u64* c) {
    const ulonglong2* v = (const ulonglong2*)c;
    ulonglong2 a = v[0], b = v[1], d = v[2];
    Coef k;
    k.sx = a.x; k.sy = a.y; k.nsy = b.x;
    k.ox = b.y; k.oy = d.x; k.noy = d.y;
    return k;
}

// new = s*a + o*p (complex, 2 packed lanes): 8 f32x2 ops
__device__ __forceinline__ void cupd(u64 X, u64 Y, u64 PX, u64 PY, const Coef& c,
                                     u64& NX, u64& NY) {
    u64 nx = mul2(c.sx, X);
    nx = fma2(c.nsy, Y, nx);
    nx = fma2(c.ox, PX, nx);
    nx = fma2(c.noy, PY, nx);
    u64 ny = mul2(c.sx, Y);
    ny = fma2(c.sy, X, ny);
    ny = fma2(c.ox, PY, ny);
    ny = fma2(c.oy, PX, ny);
    NX = nx; NY = ny;
}

// ---------------- shared memory (dynamic, ~47KB) ----------------
struct SimSmem {
    u64 coef[96 * 18];
    u64 aX[1024]; u64 aY[1024];   // single 4-bit transpose staging
    u64 cX[1024]; u64 cY[1024];   // own-half mirror for self-term gather
    u64 mbar[2];                  // double-buffered cross-CTA mbarriers
};

// ---------------------------------------------------------------------------
// Indexing: 8 sim CTAs = 4 columns x 2 halves.
// START layout per layer: amp n: lam=n0, p=n1, lane t0..t4=n2..n6,
// warp t5..t8=n7..n10, CTA r=n11. Wire w acts on bit 11-w.
// Layer: gates on bits 0..6 (wires 11..5); ONE smem transpose swapping
// {n0,n1,n2,n3}<->{n7,n8,n9,n10}; gates on n7..n10 (wires 4,3,2,1) now at
// pack/pair/lane0/lane1; global exchange fuses the wire-0 (bit 11) gate with
// the CNOT perm y -> y^(y>>1) and restores the START layout.
//
// Transpose buffer float image (with bank swizzle):
//   F(n)  = n0 | n2<<1 | n3<<2 | n4<<3 | n5<<4 | n6<<5 | n7<<6 | n8<<7
//         | n9<<8 | n10<<9 | n1<<10
//   FT(n) = F ^ ((F>>8)&1)<<1 ^ ((F>>9)&1)<<2
// Global/mirror float image (per column, 4096 floats; swizzled):
//   G(m)  = m7 | m9<<1 | m10<<2 | m4<<3 | m5<<4 | m6<<5 | m0<<6 | m1<<7
//         | m2<<8 | m3<<9 | m8<<10 | m11<<11
//   Gs(f) = f ^ ((f>>7)&1)<<1 ^ ((f>>8)&1)<<2
// ---------------------------------------------------------------------------
__device__ __forceinline__ int Gaddr(int m) {
    return ((m >> 7) & 1) | (((m >> 9) & 1) << 1) | (((m >> 10) & 1) << 2)
         | (((m >> 4) & 1) << 3) | (((m >> 5) & 1) << 4) | (((m >> 6) & 1) << 5)
         | ((m & 1) << 6) | (((m >> 1) & 1) << 7) | (((m >> 2) & 1) << 8)
         | (((m >> 3) & 1) << 9) | (((m >> 8) & 1) << 10) | (((m >> 11) & 1) << 11);
}
__device__ __forceinline__ int Gswiz(int f) {
    return f ^ (((f >> 7) & 1) << 1) ^ (((f >> 8) & 1) << 2);
}

__device__ __forceinline__ void gate_pair(u64 AX[2], u64 AY[2], const u64* cc) {
    Coef C0 = ldCoef(cc);
    Coef C1 = ldCoef(cc + 6);
    u64 x0 = AX[0], y0 = AY[0], x1 = AX[1], y1 = AY[1];
    cupd(x0, y0, x1, y1, C0, AX[0], AY[0]);
    cupd(x1, y1, x0, y0, C1, AX[1], AY[1]);
}

__device__ __forceinline__ void gate_pck(u64 AX[2], u64 AY[2], const u64* cc) {
    Coef C = ldCoef(cc + 12);
    #pragma unroll
    for (int p = 0; p < 2; p++) {
        u64 px = swap2(AX[p]), py = swap2(AY[p]);
        cupd(AX[p], AY[p], px, py, C, AX[p], AY[p]);
    }
}

template<int LM, int K>
__device__ __forceinline__ void gate_lane(u64 AX[2], u64 AY[2], const u64* cc, int t) {
    Coef C = ldCoef(cc + ((t >> K) & 1) * 6);
    #pragma unroll
    for (int p = 0; p < 2; p++) {
        u64 px = __shfl_xor_sync(0xffffffffu, AX[p], LM);
        u64 py = __shfl_xor_sync(0xffffffffu, AY[p], LM);
        cupd(AX[p], AY[p], px, py, C, AX[p], AY[p]);
    }
}

__global__ __launch_bounds__(512, 1) __cluster_dims__(2, 1, 1)
void fused_kernel(
    const float* __restrict__ weights, const float* __restrict__ head_w,
    const float* __restrict__ head_b, const float* __restrict__ sb,
    float* __restrict__ out, int B, int nOut)
{
    extern __shared__ char smem_raw[];
    const int t = threadIdx.x;
    const int bid = blockIdx.x;

    if (bid < 8) {
        // ================= SIM BLOCK (col = bid>>1, half r = bid&1) ========
        SimSmem* sm = (SimSmem*)smem_raw;
        const int col = bid >> 1;
        const int r = bid & 1;
        const unsigned peer = 1u - (unsigned)r;
        const uint32_t mb0 = smem32(&sm->mbar[0]);
        const uint32_t mb1 = smem32(&sm->mbar[1]);

        if (t < 96) {
            float phi = weights[t * 3 + 0];
            float th  = weights[t * 3 + 1];
            float om  = weights[t * 3 + 2];
            float st, ct; sincosf(th * 0.5f, &st, &ct);
            float sp, cp; sincosf((phi + om) * 0.5f, &sp, &cp);
            float sd, cd; sincosf((phi - om) * 0.5f, &sd, &cd);
            const float2 u00 = make_float2( cp * ct, -sp * ct);
            const float2 u01 = make_float2(-cd * st, -sd * st);
            const float2 u10 = make_float2( cd * st, -sd * st);
            const float2 u11 = make_float2( cp * ct,  sp * ct);
            u64* c = sm->coef + t * 18;
            c[0]  = pack2(u00.x, u00.x); c[1]  = pack2(u00.y, u00.y);
            c[2]  = pack2(-u00.y, -u00.y);
            c[3]  = pack2(u01.x, u01.x); c[4]  = pack2(u01.y, u01.y);
            c[5]  = pack2(-u01.y, -u01.y);
            c[6]  = pack2(u11.x, u11.x); c[7]  = pack2(u11.y, u11.y);
            c[8]  = pack2(-u11.y, -u11.y);
            c[9]  = pack2(u10.x, u10.x); c[10] = pack2(u10.y, u10.y);
            c[11] = pack2(-u10.y, -u10.y);
            c[12] = pack2(u00.x, u11.x); c[13] = pack2(u00.y, u11.y);
            c[14] = pack2(-u00.y, -u11.y);
            c[15] = pack2(u01.x, u10.x); c[16] = pack2(u01.y, u10.y);
            c[17] = pack2(-u01.y, -u10.y);
        }
        if (t == 0) { mbar_init(mb0, 1); mbar_init(mb1, 1); }
        __syncthreads();
        CLUSTER_ARRIVE();
        CLUSTER_WAIT();

        // init |kj>: n11 = b0 = (col>>1)&1 -> CTA r, n10 = b1 = col&1 -> t8
        u64 AX[2] = {0ull, 0ull}, AY[2] = {0ull, 0ull};
        if (r == ((col >> 1) & 1) && t == ((col & 1) << 8))
            AX[0] = pack2(1.0f, 0.0f);

        // ---- layer-invariant addresses ----
        // transpose store swizzle (u64 slot s = t or 512|t; bits 7,8 of s)
        const int sw_t = ((t >> 7) & 1) ^ (((t >> 8) & 1) << 1);
        // transpose load base: FT(n(t', p'=0, lam'=0))
        int Fb = ((t >> 5) & 1) | (((t >> 7) & 1) << 1) | (((t >> 8) & 1) << 2)
               | (((t >> 2) & 1) << 3) | (((t >> 3) & 1) << 4) | (((t >> 4) & 1) << 5)
               | ((t & 1) << 8) | (((t >> 1) & 1) << 9) | (((t >> 6) & 1) << 10);
        const int baseT = Fb ^ ((t & 1) << 1) ^ (((t >> 1) & 1) << 2);
        // global/mirror store swizzle (u64 slot bits 6,7 = t6,t7)
        const int sw_g = ((t >> 6) & 1) ^ (((t >> 7) & 1) << 1);
        // gather base: y(t, p=0, lam=0) -> m = y^(y>>1) -> swizzled G addr
        const int nb = ((t & 0x1F) << 2) | (((t >> 5) & 0xF) << 7) | (r << 11);
        const int gb = Gswiz(Gaddr((nb ^ (nb >> 1)) & 0xFFF));
        // deltas: lam flip -> 64; p flip -> Gswiz(G(3)) = 194; partner -> ^2048

        float* fAX = (float*)sm->aX; float* fAY = (float*)sm->aY;
        float* csX = (float*)sm->cX; float* csY = (float*)sm->cY;

        #pragma unroll 1
        for (int l = 0; l < 8; l++) {
            const u64* CG = sm->coef + l * 12 * 18;
            // ---- phase 1: gates on bits 0..6 (wires 11..5) ----
            gate_pck (AX, AY, CG + 11 * 18);
            gate_pair(AX, AY, CG + 10 * 18);
            gate_lane<1, 0>(AX, AY, CG + 9 * 18, t);
            gate_lane<2, 1>(AX, AY, CG + 8 * 18, t);
            gate_lane<4, 2>(AX, AY, CG + 7 * 18, t);
            gate_lane<8, 3>(AX, AY, CG + 6 * 18, t);
            gate_lane<16, 4>(AX, AY, CG + 5 * 18, t);
            // ---- single transpose: {n0..n3} <-> {n7..n10} ----
            sm->aX[t ^ sw_t] = AX[0]; sm->aX[(512 | t) ^ sw_t] = AX[1];
            sm->aY[t ^ sw_t] = AY[0]; sm->aY[(512 | t) ^ sw_t] = AY[1];
            __syncthreads();
            #pragma unroll
            for (int p = 0; p < 2; p++) {
                int a = baseT ^ (p << 7);
                AX[p] = pack2(fAX[a], fAX[a ^ 64]);
                AY[p] = pack2(fAY[a], fAY[a ^ 64]);
            }
            // gates on imported bits: lam'=n7 (wire 4), p'=n8 (wire 3),
            // t'0=n9 (wire 2), t'1=n10 (wire 1)
            gate_pck (AX, AY, CG + 4 * 18);
            gate_pair(AX, AY, CG + 3 * 18);
            gate_lane<1, 0>(AX, AY, CG + 2 * 18, t);
            gate_lane<2, 1>(AX, AY, CG + 1 * 18, t);
            // ---- exchange: own half to smem(self) + L2(peer), mbarrier sync ----
            u64* guX = g_sX[l & 1][col];
            u64* guY = g_sY[l & 1][col];
            const float* gfX = (const float*)guX;
            const float* gfY = (const float*)guY;
            {
                int s0 = ((r << 10) | t) ^ sw_g;
                int s1 = ((r << 10) | 512 | t) ^ sw_g;
                stcg64(&guX[s0], AX[0]); stcg64(&guX[s1], AX[1]);
                stcg64(&guY[s0], AY[0]); stcg64(&guY[s1], AY[1]);
                sm->cX[t ^ sw_g] = AX[0]; sm->cX[(512 | t) ^ sw_g] = AX[1];
                sm->cY[t ^ sw_g] = AY[0]; sm->cY[(512 | t) ^ sw_g] = AY[1];
            }
            __syncthreads();
            const uint32_t mb = (l & 1) ? mb1 : mb0;
            if (t == 0) mbar_arrive_peer(mb, peer);   // release: publishes .cg stores
            // self terms (own half, from smem) in the arrive/wait shadow
            Coef C = ldCoef(CG + 0 * 18 + r * 6);
            u64 TX[2], TY[2];
            int a0s[2], a1s[2];
            #pragma unroll
            for (int p = 0; p < 2; p++) {
                int a0 = gb ^ (p ? 194 : 0);
                int a1 = a0 ^ 64;
                a0s[p] = a0; a1s[p] = a1;
                u64 VX = pack2(csX[a0 & 2047], csX[a1 & 2047]);
                u64 VY = pack2(csY[a0 & 2047], csY[a1 & 2047]);
                TX[p] = fma2(C.nsy, VY, mul2(C.sx, VX));
                TY[p] = fma2(C.sy, VX, mul2(C.sx, VY));
            }
            mbar_wait(mb, (unsigned)((l >> 1) & 1));  // acquire: peer stores visible
            // peer terms (other half, via L2)
            #pragma unroll
            for (int p = 0; p < 2; p++) {
                int a0 = a0s[p] ^ 2048, a1 = a1s[p] ^ 2048;
                u64 PX = pack2(ldcg(gfX + a0), ldcg(gfX + a1));
                u64 PY = pack2(ldcg(gfY + a0), ldcg(gfY + a1));
                AX[p] = fma2(C.noy, PY, fma2(C.ox, PX, TX[p]));
                AY[p] = fma2(C.oy, PX, fma2(C.ox, PY, TY[p]));
            }
        }

        // write column (natural order)
        #pragma unroll
        for (int p = 0; p < 2; p++) {
            float2 xs = unpack2(AX[p]), ys = unpack2(AY[p]);
            int n0 = (r << 11) | (((t >> 5) & 0xF) << 7) | ((t & 0x1F) << 2) | (p << 1);
            g_v[col][n0]     = make_float2(xs.x, ys.x);
            g_v[col][n0 | 1] = make_float2(xs.y, ys.y);
        }
        __syncthreads();
        if (t == 0) red_release_add(&g_flag, 1u);
        CLUSTER_ARRIVE();
        CLUSTER_WAIT();
    } else {
        // ================= OUTPUT BLOCK =================
        const int i = (bid - 8) * 512 + t;
        float s0 = 0.f, c0 = 1.f, s1 = 0.f, c1 = 1.f, hb = head_b[0];
        if (i < B) {
            float t0 = sb[i * 8 + 0], t1 = sb[i * 8 + 1];
            sincosf(t0 * 0.5f, &s0, &c0);
            sincosf(t1 * 0.5f, &s1, &c1);
        }
        float hw[12];
        #pragma unroll
        for (int w = 0; w < 12; w++) hw[w] = head_w[w];

        if (t == 0) {
            while (ld_acquire(&g_flag) < 8u) __nanosleep(32);
        }
        __syncthreads();

        // --- Gram: G[j][k] = sum_idx s(idx) v_j conj(v_k) ---
        float2 acc[4][4];
        #pragma unroll
        for (int a = 0; a < 4; a++)
            #pragma unroll
            for (int b = 0; b < 4; b++) acc[a][b] = make_float2(0.f, 0.f);

        for (int idx = t; idx < 4096; idx += 512) {
            float s = 0.f;
            #pragma unroll
            for (int w = 0; w < 12; w++)
                s += ((idx >> (11 - w)) & 1) ? -hw[w] : hw[w];
            float2 v[4];
            #pragma unroll
            for (int a = 0; a < 4; a++) v[a] = g_v[a][idx];
            #pragma unroll
            for (int a = 0; a < 4; a++)
                #pragma unroll
                for (int b = 0; b < 4; b++) {
                    float pr = v[a].x * v[b].x + v[a].y * v[b].y;
                    float pi = v[a].y * v[b].x - v[a].x * v[b].y;
                    acc[a][b].x += s * pr;
                    acc[a][b].y += s * pi;
                }
        }

        float* red = (float*)smem_raw;      // [16][32]
        float* Gs  = red + 16 * 32;         // [32]
        float* flat = reinterpret_cast<float*>(acc);
        const int lane = t & 31, warp = t >> 5;
        #pragma unroll
        for (int comp = 0; comp < 32; comp++) {
            float v = flat[comp];
            #pragma unroll
            for (int off = 16; off; off >>= 1)
                v += __shfl_down_sync(0xffffffff, v, off);
            if (lane == 0) red[warp * 32 + comp] = v;
        }
        __syncthreads();
        if (t < 32) {
            float v = 0.f;
            #pragma unroll
            for (int w = 0; w < 16; w++) v += red[w * 32 + t];
            Gs[t] = v;
        }
        __syncthreads();

        // self-resetting flags for graph replays
        if (t == 0) {
            int d = atomicAdd(&g_done2, 1);
            if (d == nOut - 1) {
                atomicExch(&g_flag, 0u);
                atomicExch(&g_done2, 0);
            }
        }

        // --- per-sample output: out = Re(c^H G c) + bias ---
        if (i < B) {
            float2 c[4];
            c[0] = make_float2(c0 * c1, 0.f);
            c[1] = make_float2(c0 * s1, 0.f);
            c[2] = make_float2(0.f, -s0 * c1);
            c[3] = make_float2(0.f, -s0 * s1);

            float res = hb;
            #pragma unroll
            for (int jj = 0; jj < 4; jj++)
                #pragma unroll
                for (int k = 0; k < 4; k++) {
                    float ccr = c[jj].x * c[k].x + c[jj].y * c[k].y;
                    float cci = c[jj].y * c[k].x - c[jj].x * c[k].y;
                    float gx = Gs[(jj * 4 + k) * 2];
                    float gy = Gs[(jj * 4 + k) * 2 + 1];
                    res += ccr * gx - cci * gy;
                }
            out[i] = res;
        }
    }
}

extern "C" void kernel_launch(void* const* d_in, const int* in_sizes, int n_in,
                              void* d_out, int out_size) {
    const float* state_batch = (const float*)d_in[0];  // (B, 8)
    const float* weights     = (const float*)d_in[1];  // (8, 12, 3)
    const float* head_w      = (const float*)d_in[2];  // (1, 12)
    const float* head_b      = (const float*)d_in[3];  // (1,)
    float* out = (float*)d_out;
    const int B = in_sizes[0] / 8;

    const int smem_bytes = (int)sizeof(SimSmem);
    cudaFuncSetAttribute(fused_kernel, cudaFuncAttributeMaxDynamicSharedMemorySize,
                         smem_bytes);
    int nOut = (B + 511) / 512;
    nOut += (nOut & 1);   // grid must be even for cluster_dims (2,1,1)
    fused_kernel<<<8 + nOut, 512, smem_bytes>>>(weights, head_w, head_b,
                                                state_batch, out, B, nOut);
}

// round 14
// speedup vs baseline: 1.1156x; 1.1156x over previous
#include <cuda_runtime.h>
#include <cuda_bf16.h>
#include <cstdint>

typedef unsigned long long u64;

// Cross-block scratch (no allocations allowed -> __device__ globals)
__device__ float2 g_v[4][4096];       // 4 columns of the circuit unitary
__device__ u64 g_sX[2][4][2048];      // double-buffered per-column staging, X
__device__ u64 g_sY[2][4][2048];      // double-buffered per-column staging, Y
__device__ unsigned g_flag = 0;       // sim-done counter (target 8)
__device__ int g_done2 = 0;           // output-blocks-passed-spin counter

// ---------------- f32x2 packed helpers ----------------
__device__ __forceinline__ u64 pack2(float x, float y) {
    u64 u; asm("mov.b64 %0, {%1,%2};" : "=l"(u) : "f"(x), "f"(y)); return u;
}
__device__ __forceinline__ float2 unpack2(u64 u) {
    float2 v; asm("mov.b64 {%0,%1}, %2;" : "=f"(v.x), "=f"(v.y) : "l"(u)); return v;
}
__device__ __forceinline__ u64 swap2(u64 u) {
    float2 v = unpack2(u); return pack2(v.y, v.x);
}
__device__ __forceinline__ u64 fma2(u64 a, u64 b, u64 c) {
    u64 d; asm("fma.rn.f32x2 %0, %1, %2, %3;" : "=l"(d) : "l"(a), "l"(b), "l"(c)); return d;
}
__device__ __forceinline__ u64 mul2(u64 a, u64 b) {
    u64 d; asm("mul.rn.f32x2 %0, %1, %2;" : "=l"(d) : "l"(a), "l"(b)); return d;
}
__device__ __forceinline__ float ldcg(const float* p) {
    float v; asm volatile("ld.global.cg.f32 %0, [%1];" : "=f"(v) : "l"(p)); return v;
}
__device__ __forceinline__ void stcg64(u64* p, u64 v) {
    asm volatile("st.global.cg.b64 [%0], %1;" :: "l"(p), "l"(v));
}
__device__ __forceinline__ void red_release_add(unsigned* p, unsigned v) {
    asm volatile("red.release.gpu.global.add.u32 [%0], %1;" :: "l"(p), "r"(v) : "memory");
}
__device__ __forceinline__ unsigned ld_acquire(const unsigned* p) {
    unsigned v;
    asm volatile("ld.acquire.gpu.global.u32 %0, [%1];" : "=r"(v) : "l"(p) : "memory");
    return v;
}
__device__ __forceinline__ float2 cmulf(float2 a, float2 b) {
    return make_float2(a.x * b.x - a.y * b.y, a.x * b.y + a.y * b.x);
}

// ---------------- cluster / mbarrier helpers ----------------
__device__ __forceinline__ uint32_t smem32(const void* p) {
    uint32_t a;
    asm("{ .reg .u64 t; cvta.to.shared.u64 t, %1; cvt.u32.u64 %0, t; }"
        : "=r"(a) : "l"(p));
    return a;
}
__device__ __forceinline__ void mbar_init(uint32_t a, unsigned cnt) {
    asm volatile("mbarrier.init.shared.b64 [%0], %1;" :: "r"(a), "r"(cnt) : "memory");
}
__device__ __forceinline__ void mbar_arrive_peer(uint32_t a, unsigned peer) {
    asm volatile(
        "{\n\t.reg .b32 ra;\n\t"
        "mapa.shared::cluster.u32 ra, %0, %1;\n\t"
        "mbarrier.arrive.release.cluster.shared::cluster.b64 _, [ra];\n\t}"
        :: "r"(a), "r"(peer) : "memory");
}
__device__ __forceinline__ void mbar_wait(uint32_t a, unsigned parity) {
    asm volatile(
        "{\n\t.reg .pred P;\n\t"
        "W%=:\n\t"
        "mbarrier.try_wait.parity.acquire.cluster.shared::cta.b64 P, [%0], %1;\n\t"
        "@P bra.uni D%=;\n\t"
        "bra.uni W%=;\n\t"
        "D%=:\n\t}"
        :: "r"(a), "r"(parity) : "memory");
}
#define CLUSTER_ARRIVE() asm volatile("barrier.cluster.arrive.aligned;" ::: "memory")
#define CLUSTER_WAIT()   asm volatile("barrier.cluster.wait.aligned;" ::: "memory")

struct Coef { u64 sx, sy, nsy, ox, oy, noy; };

// 16B-aligned blocks (stride 144B per gate, sub-blocks at +0/+48/+96) -> LDS.128
__device__ __forceinline__ Coef ldCoef(const u64* c) {
    const ulonglong2* v = (const ulonglong2*)c;
    ulonglong2 a = v[0], b = v[1], d = v[2];
    Coef k;
    k.sx = a.x; k.sy = a.y; k.nsy = b.x;
    k.ox = b.y; k.oy = d.x; k.noy = d.y;
    return k;
}

// new = s*a + o*p (complex, 2 packed lanes): 8 f32x2 ops
__device__ __forceinline__ void cupd(u64 X, u64 Y, u64 PX, u64 PY, const Coef& c,
                                     u64& NX, u64& NY) {
    u64 nx = mul2(c.sx, X);
    nx = fma2(c.nsy, Y, nx);
    nx = fma2(c.ox, PX, nx);
    nx = fma2(c.noy, PY, nx);
    u64 ny = mul2(c.sx, Y);
    ny = fma2(c.sy, X, ny);
    ny = fma2(c.ox, PY, ny);
    ny = fma2(c.oy, PX, ny);
    NX = nx; NY = ny;
}

// ---------------- shared memory (dynamic, ~63KB) ----------------
struct SimSmem {
    u64 coef[96 * 18];
    float2 rawu[48];              // raw 2x2 matrices of layer-0 gates
    u64 aX[1024]; u64 aY[1024];   // local transpose A staging
    u64 bX[1024]; u64 bY[1024];   // local transpose B staging
    u64 cX[1024]; u64 cY[1024];   // own-half mirror for self-term gather
    u64 mbar[2];                  // double-buffered cross-CTA mbarriers
};

// ---------------------------------------------------------------------------
// Indexing: 8 sim CTAs = 4 columns x 2 halves (identical to R12, which passed).
// Natural amp n: lam=n0, p=n1, t0..t4=n2..n6, t5..t8=n7..n10, r=n11.
// Per layer: gates bits 0..6; transpose A -> gates 9,10; transpose B -> gates
// 7,8; then exchange fusing the bit-11 gate (branch=r) with CNOT perm.
// Exchange-time register<->amp map (from store slot = t|p<<9|r<<10 and Gaddr):
//   lam=m7, p=m8, t0..4=m2..6, t5=m9, t6=m10, t7=m0, t8=m1, r=m11.
// Layer 0 is computed analytically: after the first 11 gates the state is a
// product state, amp(m) = [m11==b0] * prod_{w=1..11} u_w[m_bit][k_bit]
// (k: bit11=b0 wire0 handled by the exchange, bit10=b1 -> wire 1, rest 0).
// ---------------------------------------------------------------------------

__device__ __forceinline__ void gate_pair(u64 AX[2], u64 AY[2], const u64* cc) {
    Coef C0 = ldCoef(cc);
    Coef C1 = ldCoef(cc + 6);
    u64 x0 = AX[0], y0 = AY[0], x1 = AX[1], y1 = AY[1];
    cupd(x0, y0, x1, y1, C0, AX[0], AY[0]);
    cupd(x1, y1, x0, y0, C1, AX[1], AY[1]);
}

__device__ __forceinline__ void gate_pck(u64 AX[2], u64 AY[2], const u64* cc) {
    Coef C = ldCoef(cc + 12);
    #pragma unroll
    for (int p = 0; p < 2; p++) {
        u64 px = swap2(AX[p]), py = swap2(AY[p]);
        cupd(AX[p], AY[p], px, py, C, AX[p], AY[p]);
    }
}

template<int LM, int K>
__device__ __forceinline__ void gate_lane(u64 AX[2], u64 AY[2], const u64* cc, int t) {
    Coef C = ldCoef(cc + ((t >> K) & 1) * 6);
    #pragma unroll
    for (int p = 0; p < 2; p++) {
        u64 px = __shfl_xor_sync(0xffffffffu, AX[p], LM);
        u64 py = __shfl_xor_sync(0xffffffffu, AY[p], LM);
        cupd(AX[p], AY[p], px, py, C, AX[p], AY[p]);
    }
}

// Global/smem staging float address of natural amp m (per column):
// G(m) = m7 | (m2..6<<1) | (m9<<6) | (m10<<7) | (m0<<8) | (m1<<9) | (m8<<10) | (m11<<11)
__device__ __forceinline__ int Gaddr(int m) {
    return ((m >> 7) & 1) | (((m >> 2) & 0x1F) << 1) | (((m >> 9) & 1) << 6)
         | (((m >> 10) & 1) << 7) | ((m & 1) << 8) | (((m >> 1) & 1) << 9)
         | (((m >> 8) & 1) << 10) | (((m >> 11) & 1) << 11);
}

__global__ __launch_bounds__(512, 1) __cluster_dims__(2, 1, 1)
void fused_kernel(
    const float* __restrict__ weights, const float* __restrict__ head_w,
    const float* __restrict__ head_b, const float* __restrict__ sb,
    float* __restrict__ out, int B, int nOut)
{
    extern __shared__ char smem_raw[];
    const int t = threadIdx.x;
    const int bid = blockIdx.x;

    if (bid < 8) {
        // ================= SIM BLOCK (col = bid>>1, half r = bid&1) ========
        SimSmem* sm = (SimSmem*)smem_raw;
        const int col = bid >> 1;
        const int r = bid & 1;
        const int b0 = (col >> 1) & 1;
        const int b1 = col & 1;
        const unsigned peer = 1u - (unsigned)r;
        const uint32_t mb0 = smem32(&sm->mbar[0]);
        const uint32_t mb1 = smem32(&sm->mbar[1]);

        if (t < 96) {
            float phi = weights[t * 3 + 0];
            float th  = weights[t * 3 + 1];
            float om  = weights[t * 3 + 2];
            float st, ct; sincosf(th * 0.5f, &st, &ct);
            float sp, cp; sincosf((phi + om) * 0.5f, &sp, &cp);
            float sd, cd; sincosf((phi - om) * 0.5f, &sd, &cd);
            const float2 u00 = make_float2( cp * ct, -sp * ct);
            const float2 u01 = make_float2(-cd * st, -sd * st);
            const float2 u10 = make_float2( cd * st, -sd * st);
            const float2 u11 = make_float2( cp * ct,  sp * ct);
            u64* c = sm->coef + t * 18;
            c[0]  = pack2(u00.x, u00.x); c[1]  = pack2(u00.y, u00.y);
            c[2]  = pack2(-u00.y, -u00.y);
            c[3]  = pack2(u01.x, u01.x); c[4]  = pack2(u01.y, u01.y);
            c[5]  = pack2(-u01.y, -u01.y);
            c[6]  = pack2(u11.x, u11.x); c[7]  = pack2(u11.y, u11.y);
            c[8]  = pack2(-u11.y, -u11.y);
            c[9]  = pack2(u10.x, u10.x); c[10] = pack2(u10.y, u10.y);
            c[11] = pack2(-u10.y, -u10.y);
            c[12] = pack2(u00.x, u11.x); c[13] = pack2(u00.y, u11.y);
            c[14] = pack2(-u00.y, -u11.y);
            c[15] = pack2(u01.x, u10.x); c[16] = pack2(u01.y, u10.y);
            c[17] = pack2(-u01.y, -u10.y);
            if (t < 12) {   // raw matrices of layer-0 gates for the analytic init
                sm->rawu[t * 4 + 0] = u00;
                sm->rawu[t * 4 + 1] = u01;
                sm->rawu[t * 4 + 2] = u10;
                sm->rawu[t * 4 + 3] = u11;
            }
        }
        if (t == 0) { mbar_init(mb0, 1); mbar_init(mb1, 1); }
        __syncthreads();
        CLUSTER_ARRIVE();
        CLUSTER_WAIT();

        u64 AX[2] = {0ull, 0ull}, AY[2] = {0ull, 0ull};

        // layer-invariant addresses (verbatim R12)
        const int baseA = ((t & 0x7F) << 1) | ((t >> 7) & 1) | (((t >> 8) & 1) << 10);
        const int baseB = ((t >> 5) & 1) | ((t & 0x1F) << 1)
                        | (((t >> 7) & 1) << 8) | (((t >> 8) & 1) << 9)
                        | (((t >> 6) & 1) << 10);
        const int nb = ((t & 0x1F) << 2) | (((t >> 5) & 0xF) << 7) | (r << 11);
        const int gb = Gaddr((nb ^ (nb >> 1)) & 0xFFF);

        float* fAX = (float*)sm->aX; float* fAY = (float*)sm->aY;
        float* fBX = (float*)sm->bX; float* fBY = (float*)sm->bY;
        float* csX = (float*)sm->cX; float* csY = (float*)sm->cY;

        #pragma unroll 1
        for (int l = 0; l < 8; l++) {
            const u64* CG = sm->coef + l * 12 * 18;
            if (l == 0) {
                // ---- analytic layer 0 (first 11 gates), exchange layout ----
                if (r == b0) {
                    const float2* RU = sm->rawu;
                    float2 P = RU[4 * 1 + 2 * ((t >> 6) & 1) + b1];   // wire 1, m10=t6
                    P = cmulf(P, RU[4 * 2  + 2 * ((t >> 5) & 1)]);    // wire 2, m9=t5
                    P = cmulf(P, RU[4 * 5  + 2 * ((t >> 4) & 1)]);    // wire 5, m6=t4
                    P = cmulf(P, RU[4 * 6  + 2 * ((t >> 3) & 1)]);    // wire 6, m5=t3
                    P = cmulf(P, RU[4 * 7  + 2 * ((t >> 2) & 1)]);    // wire 7, m4=t2
                    P = cmulf(P, RU[4 * 8  + 2 * ((t >> 1) & 1)]);    // wire 8, m3=t1
                    P = cmulf(P, RU[4 * 9  + 2 * (t & 1)]);           // wire 9, m2=t0
                    P = cmulf(P, RU[4 * 10 + 2 * ((t >> 8) & 1)]);    // wire 10, m1=t8
                    P = cmulf(P, RU[4 * 11 + 2 * ((t >> 7) & 1)]);    // wire 11, m0=t7
                    #pragma unroll
                    for (int p = 0; p < 2; p++) {
                        float2 Q  = cmulf(P, RU[4 * 3 + 2 * p]);      // wire 3, m8=p
                        float2 a0 = cmulf(Q, RU[4 * 4 + 0]);          // wire 4, m7=0
                        float2 a1 = cmulf(Q, RU[4 * 4 + 2]);          // wire 4, m7=1
                        AX[p] = pack2(a0.x, a1.x);
                        AY[p] = pack2(a0.y, a1.y);
                    }
                } else {
                    AX[0] = AX[1] = AY[0] = AY[1] = 0ull;
                }
            } else {
                // ---- gates on bits 0..6 (wires 11..5) ----
                gate_pck (AX, AY, CG + 11 * 18);
                gate_pair(AX, AY, CG + 10 * 18);
                gate_lane<1, 0>(AX, AY, CG + 9 * 18, t);
                gate_lane<2, 1>(AX, AY, CG + 8 * 18, t);
                gate_lane<4, 2>(AX, AY, CG + 7 * 18, t);
                gate_lane<8, 3>(AX, AY, CG + 6 * 18, t);
                gate_lane<16, 4>(AX, AY, CG + 5 * 18, t);
                // ---- transpose A: (lam,p) <-> (n9,n10) ----
                sm->aX[t] = AX[0]; sm->aX[512 + t] = AX[1];
                sm->aY[t] = AY[0]; sm->aY[512 + t] = AY[1];
                __syncthreads();
                #pragma unroll
                for (int p = 0; p < 2; p++) {
                    int a = baseA ^ (p << 9);
                    AX[p] = pack2(fAX[a], fAX[a ^ 256]);
                    AY[p] = pack2(fAY[a], fAY[a ^ 256]);
                }
                gate_pck (AX, AY, CG + 2 * 18);
                gate_pair(AX, AY, CG + 1 * 18);
                // ---- transpose B: (lam,p) <-> (n7,n8) ----
                sm->bX[t] = AX[0]; sm->bX[512 + t] = AX[1];
                sm->bY[t] = AY[0]; sm->bY[512 + t] = AY[1];
                __syncthreads();
                #pragma unroll
                for (int p = 0; p < 2; p++) {
                    int a = baseB ^ (p << 7);
                    AX[p] = pack2(fBX[a], fBX[a ^ 64]);
                    AY[p] = pack2(fBY[a], fBY[a ^ 64]);
                }
                gate_pck (AX, AY, CG + 4 * 18);
                gate_pair(AX, AY, CG + 3 * 18);
            }
            // ---- exchange: own half to smem(self) + L2(peer), mbarrier sync ----
            u64* guX = g_sX[l & 1][col];
            u64* guY = g_sY[l & 1][col];
            const float* gfX = (const float*)guX;
            const float* gfY = (const float*)guY;
            stcg64(&guX[(r << 10) | t], AX[0]);
            stcg64(&guX[(r << 10) | 512 | t], AX[1]);
            stcg64(&guY[(r << 10) | t], AY[0]);
            stcg64(&guY[(r << 10) | 512 | t], AY[1]);
            sm->cX[t] = AX[0]; sm->cX[512 + t] = AX[1];
            sm->cY[t] = AY[0]; sm->cY[512 + t] = AY[1];
            __syncthreads();
            const uint32_t mb = (l & 1) ? mb1 : mb0;
            if (t == 0) mbar_arrive_peer(mb, peer);   // release: publishes .cg stores
            // self terms (own half, from smem) in the arrive/wait shadow
            Coef C = ldCoef(CG + 0 * 18 + r * 6);
            u64 TX[2], TY[2];
            int a0s[2], a1s[2];
            #pragma unroll
            for (int p = 0; p < 2; p++) {
                int a0 = gb ^ (p ? 768 : 0);
                int a1 = a0 ^ 256;
                a0s[p] = a0; a1s[p] = a1;
                u64 VX = pack2(csX[a0 & 2047], csX[a1 & 2047]);
                u64 VY = pack2(csY[a0 & 2047], csY[a1 & 2047]);
                TX[p] = fma2(C.nsy, VY, mul2(C.sx, VX));
                TY[p] = fma2(C.sy, VX, mul2(C.sx, VY));
            }
            mbar_wait(mb, (unsigned)((l >> 1) & 1));  // acquire: peer stores visible
            // peer terms (other half, via L2)
            #pragma unroll
            for (int p = 0; p < 2; p++) {
                int a0 = a0s[p] ^ 2048, a1 = a1s[p] ^ 2048;
                u64 PX = pack2(ldcg(gfX + a0), ldcg(gfX + a1));
                u64 PY = pack2(ldcg(gfY + a0), ldcg(gfY + a1));
                AX[p] = fma2(C.noy, PY, fma2(C.ox, PX, TX[p]));
                AY[p] = fma2(C.oy, PX, fma2(C.ox, PY, TY[p]));
            }
        }

        // write column (natural order)
        #pragma unroll
        for (int p = 0; p < 2; p++) {
            float2 xs = unpack2(AX[p]), ys = unpack2(AY[p]);
            int n0 = (r << 11) | (((t >> 5) & 0xF) << 7) | ((t & 0x1F) << 2) | (p << 1);
            g_v[col][n0]     = make_float2(xs.x, ys.x);
            g_v[col][n0 | 1] = make_float2(xs.y, ys.y);
        }
        __syncthreads();
        if (t == 0) red_release_add(&g_flag, 1u);
        CLUSTER_ARRIVE();
        CLUSTER_WAIT();
    } else {
        // ================= OUTPUT BLOCK =================
        const int i = (bid - 8) * 512 + t;
        float s0 = 0.f, c0 = 1.f, s1 = 0.f, c1 = 1.f, hb = head_b[0];
        if (i < B) {
            float t0 = sb[i * 8 + 0], t1 = sb[i * 8 + 1];
            sincosf(t0 * 0.5f, &s0, &c0);
            sincosf(t1 * 0.5f, &s1, &c1);
        }
        float hw[12];
        #pragma unroll
        for (int w = 0; w < 12; w++) hw[w] = head_w[w];

        if (t == 0) {
            while (ld_acquire(&g_flag) < 8u) __nanosleep(32);
        }
        __syncthreads();

        // --- Gram: G[j][k] = sum_idx s(idx) v_j conj(v_k) ---
        float2 acc[4][4];
        #pragma unroll
        for (int a = 0; a < 4; a++)
            #pragma unroll
            for (int b = 0; b < 4; b++) acc[a][b] = make_float2(0.f, 0.f);

        for (int idx = t; idx < 4096; idx += 512) {
            float s = 0.f;
            #pragma unroll
            for (int w = 0; w < 12; w++)
                s += ((idx >> (11 - w)) & 1) ? -hw[w] : hw[w];
            float2 v[4];
            #pragma unroll
            for (int a = 0; a < 4; a++) v[a] = g_v[a][idx];
            #pragma unroll
            for (int a = 0; a < 4; a++)
                #pragma unroll
                for (int b = 0; b < 4; b++) {
                    float pr = v[a].x * v[b].x + v[a].y * v[b].y;
                    float pi = v[a].y * v[b].x - v[a].x * v[b].y;
                    acc[a][b].x += s * pr;
                    acc[a][b].y += s * pi;
                }
        }

        float* red = (float*)smem_raw;      // [16][32]
        float* Gs  = red + 16 * 32;         // [32]
        float* flat = reinterpret_cast<float*>(acc);
        const int lane = t & 31, warp = t >> 5;
        #pragma unroll
        for (int comp = 0; comp < 32; comp++) {
            float v = flat[comp];
            #pragma unroll
            for (int off = 16; off; off >>= 1)
                v += __shfl_down_sync(0xffffffff, v, off);
            if (lane == 0) red[warp * 32 + comp] = v;
        }
        __syncthreads();
        if (t < 32) {
            float v = 0.f;
            #pragma unroll
            for (int w = 0; w < 16; w++) v += red[w * 32 + t];
            Gs[t] = v;
        }
        __syncthreads();

        // self-resetting flags for graph replays
        if (t == 0) {
            int d = atomicAdd(&g_done2, 1);
            if (d == nOut - 1) {
                atomicExch(&g_flag, 0u);
                atomicExch(&g_done2, 0);
            }
        }

        // --- per-sample output: out = Re(c^H G c) + bias ---
        if (i < B) {
            float2 c[4];
            c[0] = make_float2(c0 * c1, 0.f);
            c[1] = make_float2(c0 * s1, 0.f);
            c[2] = make_float2(0.f, -s0 * c1);
            c[3] = make_float2(0.f, -s0 * s1);

            float res = hb;
            #pragma unroll
            for (int jj = 0; jj < 4; jj++)
                #pragma unroll
                for (int k = 0; k < 4; k++) {
                    float ccr = c[jj].x * c[k].x + c[jj].y * c[k].y;
                    float cci = c[jj].y * c[k].x - c[jj].x * c[k].y;
                    float gx = Gs[(jj * 4 + k) * 2];
                    float gy = Gs[(jj * 4 + k) * 2 + 1];
                    res += ccr * gx - cci * gy;
                }
            out[i] = res;
        }
    }
}

extern "C" void kernel_launch(void* const* d_in, const int* in_sizes, int n_in,
                              void* d_out, int out_size) {
    const float* state_batch = (const float*)d_in[0];  // (B, 8)
    const float* weights     = (const float*)d_in[1];  // (8, 12, 3)
    const float* head_w      = (const float*)d_in[2];  // (1, 12)
    const float* head_b      = (const float*)d_in[3];  // (1,)
    float* out = (float*)d_out;
    const int B = in_sizes[0] / 8;

    const int smem_bytes = (int)sizeof(SimSmem);
    cudaFuncSetAttribute(fused_kernel, cudaFuncAttributeMaxDynamicSharedMemorySize,
                         smem_bytes);
    int nOut = (B + 511) / 512;
    nOut += (nOut & 1);   // grid must be even for cluster_dims (2,1,1)
    fused_kernel<<<8 + nOut, 512, smem_bytes>>>(weights, head_w, head_b,
                                                state_batch, out, B, nOut);
}

// round 15
// speedup vs baseline: 1.2696x; 1.1380x over previous
#include <cuda_runtime.h>
#include <cuda_bf16.h>
#include <cstdint>

typedef unsigned long long u64;

// Cross-block scratch (no allocations allowed -> __device__ globals)
__device__ float2 g_v[4][4096];       // 4 columns of the circuit unitary
__device__ u64 g_sX[2][4][2048];      // double-buffered per-column staging, X
__device__ u64 g_sY[2][4][2048];      // double-buffered per-column staging, Y
__device__ unsigned g_flag = 0;       // sim-done counter (target 8)
__device__ int g_done2 = 0;           // output-blocks-passed-spin counter

// ---------------- f32x2 packed helpers ----------------
__device__ __forceinline__ u64 pack2(float x, float y) {
    u64 u; asm("mov.b64 %0, {%1,%2};" : "=l"(u) : "f"(x), "f"(y)); return u;
}
__device__ __forceinline__ float2 unpack2(u64 u) {
    float2 v; asm("mov.b64 {%0,%1}, %2;" : "=f"(v.x), "=f"(v.y) : "l"(u)); return v;
}
__device__ __forceinline__ u64 swap2(u64 u) {
    float2 v = unpack2(u); return pack2(v.y, v.x);
}
__device__ __forceinline__ u64 fma2(u64 a, u64 b, u64 c) {
    u64 d; asm("fma.rn.f32x2 %0, %1, %2, %3;" : "=l"(d) : "l"(a), "l"(b), "l"(c)); return d;
}
__device__ __forceinline__ u64 mul2(u64 a, u64 b) {
    u64 d; asm("mul.rn.f32x2 %0, %1, %2;" : "=l"(d) : "l"(a), "l"(b)); return d;
}
__device__ __forceinline__ float ldcg(const float* p) {
    float v; asm volatile("ld.global.cg.f32 %0, [%1];" : "=f"(v) : "l"(p)); return v;
}
__device__ __forceinline__ void stcg64(u64* p, u64 v) {
    asm volatile("st.global.cg.b64 [%0], %1;" :: "l"(p), "l"(v));
}
__device__ __forceinline__ void red_release_add(unsigned* p, unsigned v) {
    asm volatile("red.release.gpu.global.add.u32 [%0], %1;" :: "l"(p), "r"(v) : "memory");
}
__device__ __forceinline__ unsigned ld_acquire(const unsigned* p) {
    unsigned v;
    asm volatile("ld.acquire.gpu.global.u32 %0, [%1];" : "=r"(v) : "l"(p) : "memory");
    return v;
}
__device__ __forceinline__ float2 cmulf(float2 a, float2 b) {
    return make_float2(a.x * b.x - a.y * b.y, a.x * b.y + a.y * b.x);
}

// ---------------- cluster / mbarrier helpers ----------------
__device__ __forceinline__ uint32_t smem32(const void* p) {
    uint32_t a;
    asm("{ .reg .u64 t; cvta.to.shared.u64 t, %1; cvt.u32.u64 %0, t; }"
        : "=r"(a) : "l"(p));
    return a;
}
__device__ __forceinline__ void mbar_init(uint32_t a, unsigned cnt) {
    asm volatile("mbarrier.init.shared.b64 [%0], %1;" :: "r"(a), "r"(cnt) : "memory");
}
__device__ __forceinline__ void mbar_arrive_peer(uint32_t a, unsigned peer) {
    asm volatile(
        "{\n\t.reg .b32 ra;\n\t"
        "mapa.shared::cluster.u32 ra, %0, %1;\n\t"
        "mbarrier.arrive.release.cluster.shared::cluster.b64 _, [ra];\n\t}"
        :: "r"(a), "r"(peer) : "memory");
}
__device__ __forceinline__ void mbar_wait(uint32_t a, unsigned parity) {
    asm volatile(
        "{\n\t.reg .pred P;\n\t"
        "W%=:\n\t"
        "mbarrier.try_wait.parity.acquire.cluster.shared::cta.b64 P, [%0], %1;\n\t"
        "@P bra.uni D%=;\n\t"
        "bra.uni W%=;\n\t"
        "D%=:\n\t}"
        :: "r"(a), "r"(parity) : "memory");
}
#define CLUSTER_ARRIVE() asm volatile("barrier.cluster.arrive.aligned;" ::: "memory")
#define CLUSTER_WAIT()   asm volatile("barrier.cluster.wait.aligned;" ::: "memory")

// ---------------- shared memory (dynamic, ~66KB) ----------------
// Real-RY coef block per gate (4 u64, 32B): [0]=cs=(c,c), [1]=coA=(-s,-s),
// [2]=coB=(s,s), [3]=coP=(-s,s).
struct SimSmem {
    u64 coef[96 * 4];               // real RY coefficients
    float2 rawu[48];                // raw complex 2x2 of layer-0 gates
    float2 ry0[8];                  // (cos th/2, sin th/2) of wire-0 gates
    float2 eph[96];                 // e^{+i phi/2} per gate
    float2 eom[96];                 // e^{+i omega/2} per gate
    float2 tabA[8][128];            // diag factor tables, y bits 0..6
    float2 tabB[8][64];             // diag factor tables, y bits 6..11
    u64 aX[1024]; u64 aY[1024];     // local transpose A staging
    u64 bX[1024]; u64 bY[1024];     // local transpose B staging
    u64 cX[1024]; u64 cY[1024];     // own-half mirror for self-term gather
    u64 mbar[2];                    // double-buffered cross-CTA mbarriers
};

// ---------------------------------------------------------------------------
// Layout identical to R12/R14 (passing): amp n: lam=n0, p=n1, t0..t4=n2..n6,
// t5..t8=n7..n10, r=n11. Wire w acts on bit 11-w.
// Rot = RZ(omega) RY(theta) RZ(phi): per layer L = Omega * (RY tensor) * Phi
// with Omega/Phi diagonal. Diagonals are folded into per-exchange tables:
// F_l(y) = Omegafac_l(sigma(y)) * Phifac_{l+1}(y),  sigma(y)=y^(y>>1),
// factorized as tabA_l[y&127] * tabB_l[y>>6]. Phase gates are pure real RY.
// Layer 0 is fully analytic (incl. wire 0 + CNOT perm + Phi_1); exchanges run
// for l=1..7 with parity ((l-1)>>1)&1.
// ---------------------------------------------------------------------------

__device__ __forceinline__ void gate_pair(u64 AX[2], u64 AY[2], const u64* cc) {
    u64 cs = cc[0], coA = cc[1], coB = cc[2];
    u64 x0 = AX[0], y0 = AY[0], x1 = AX[1], y1 = AY[1];
    AX[0] = fma2(coA, x1, mul2(cs, x0));
    AY[0] = fma2(coA, y1, mul2(cs, y0));
    AX[1] = fma2(coB, x0, mul2(cs, x1));
    AY[1] = fma2(coB, y0, mul2(cs, y1));
}

__device__ __forceinline__ void gate_pck(u64 AX[2], u64 AY[2], const u64* cc) {
    u64 cs = cc[0], coP = cc[3];
    #pragma unroll
    for (int p = 0; p < 2; p++) {
        u64 px = swap2(AX[p]), py = swap2(AY[p]);
        AX[p] = fma2(coP, px, mul2(cs, AX[p]));
        AY[p] = fma2(coP, py, mul2(cs, AY[p]));
    }
}

template<int LM, int K>
__device__ __forceinline__ void gate_lane(u64 AX[2], u64 AY[2], const u64* cc, int t) {
    u64 cs = cc[0];
    u64 co = ((t >> K) & 1) ? cc[2] : cc[1];
    #pragma unroll
    for (int p = 0; p < 2; p++) {
        u64 px = __shfl_xor_sync(0xffffffffu, AX[p], LM);
        u64 py = __shfl_xor_sync(0xffffffffu, AY[p], LM);
        AX[p] = fma2(co, px, mul2(cs, AX[p]));
        AY[p] = fma2(co, py, mul2(cs, AY[p]));
    }
}

// Global/smem staging float address of natural amp m (per column) — R12 map:
__device__ __forceinline__ int Gaddr(int m) {
    return ((m >> 7) & 1) | (((m >> 2) & 0x1F) << 1) | (((m >> 9) & 1) << 6)
         | (((m >> 10) & 1) << 7) | ((m & 1) << 8) | (((m >> 1) & 1) << 9)
         | (((m >> 8) & 1) << 10) | (((m >> 11) & 1) << 11);
}

__device__ __forceinline__ float2 facsel(float2 e, int bit) {
    return bit ? e : make_float2(e.x, -e.y);
}

__global__ __launch_bounds__(512, 1) __cluster_dims__(2, 1, 1)
void fused_kernel(
    const float* __restrict__ weights, const float* __restrict__ head_w,
    const float* __restrict__ head_b, const float* __restrict__ sb,
    float* __restrict__ out, int B, int nOut)
{
    extern __shared__ char smem_raw[];
    const int t = threadIdx.x;
    const int bid = blockIdx.x;

    if (bid < 8) {
        // ================= SIM BLOCK (col = bid>>1, half r = bid&1) ========
        SimSmem* sm = (SimSmem*)smem_raw;
        const int col = bid >> 1;
        const int r = bid & 1;
        const int b0 = (col >> 1) & 1;
        const int b1 = col & 1;
        const unsigned peer = 1u - (unsigned)r;
        const uint32_t mb0 = smem32(&sm->mbar[0]);
        const uint32_t mb1 = smem32(&sm->mbar[1]);

        if (t < 96) {
            int l = t / 12, w = t % 12;
            float phi = weights[t * 3 + 0];
            float th  = weights[t * 3 + 1];
            float om  = weights[t * 3 + 2];
            float st, ct; sincosf(th * 0.5f, &st, &ct);
            float sphi, cphi; sincosf(phi * 0.5f, &sphi, &cphi);
            float som, com; sincosf(om * 0.5f, &som, &com);
            u64* c = sm->coef + t * 4;
            c[0] = pack2(ct, ct);
            c[1] = pack2(-st, -st);
            c[2] = pack2(st, st);
            c[3] = pack2(-st, st);
            sm->eph[t] = make_float2(cphi, sphi);
            sm->eom[t] = make_float2(com, som);
            if (w == 0) sm->ry0[l] = make_float2(ct, st);
            if (l == 0) {
                float cp = cphi * com - sphi * som, sp = sphi * com + cphi * som;
                float cd = cphi * com + sphi * som, sd = sphi * com - cphi * som;
                sm->rawu[w * 4 + 0] = make_float2( cp * ct, -sp * ct);
                sm->rawu[w * 4 + 1] = make_float2(-cd * st, -sd * st);
                sm->rawu[w * 4 + 2] = make_float2( cd * st, -sd * st);
                sm->rawu[w * 4 + 3] = make_float2( cp * ct,  sp * ct);
            }
        }
        if (t == 0) { mbar_init(mb0, 1); mbar_init(mb1, 1); }
        __syncthreads();

        // ---- build diag tables: F_l = Omega_l(sigma(y)) * Phi_{l+1}(y) ----
        for (int e = t; e < 1536; e += 512) {
            int l = e / 192;
            int i = e - l * 192;
            float2 v = make_float2(1.f, 0.f);
            if (i < 128) {                       // A_l: y bits 0..6, wires 6..11
                #pragma unroll
                for (int j = 0; j < 6; j++) {
                    int w = 11 - j;
                    if (l > 0) {
                        int mb = ((i >> j) ^ (i >> (j + 1))) & 1;
                        v = cmulf(v, facsel(sm->eom[l * 12 + w], mb));
                    }
                    if (l < 7) {
                        int yb = (i >> j) & 1;
                        v = cmulf(v, facsel(sm->eph[(l + 1) * 12 + w], yb));
                    }
                }
                sm->tabA[l][i] = v;
            } else {                              // B_l: y bits 6..11, wires 0..5
                int b = i - 128;
                if (l > 0) {
                    #pragma unroll
                    for (int j = 6; j < 11; j++) {
                        int w = 11 - j;
                        int mb = ((b >> (j - 6)) ^ (b >> (j - 5))) & 1;
                        v = cmulf(v, facsel(sm->eom[l * 12 + w], mb));
                    }
                    v = cmulf(v, facsel(sm->eom[l * 12 + 0], (b >> 5) & 1)); // m11
                }
                if (l < 7) {
                    #pragma unroll
                    for (int j = 6; j < 12; j++) {
                        int w = 11 - j;
                        int yb = (b >> (j - 6)) & 1;
                        v = cmulf(v, facsel(sm->eph[(l + 1) * 12 + w], yb));
                    }
                }
                sm->tabB[l][b] = v;
            }
        }
        __syncthreads();
        CLUSTER_ARRIVE();
        CLUSTER_WAIT();

        // layer-invariant addresses (verbatim R12)
        const int baseA = ((t & 0x7F) << 1) | ((t >> 7) & 1) | (((t >> 8) & 1) << 10);
        const int baseB = ((t >> 5) & 1) | ((t & 0x1F) << 1)
                        | (((t >> 7) & 1) << 8) | (((t >> 8) & 1) << 9)
                        | (((t >> 6) & 1) << 10);
        const int nb = ((t & 0x1F) << 2) | (((t >> 5) & 0xF) << 7) | (r << 11);
        const int gb = Gaddr((nb ^ (nb >> 1)) & 0xFFF);
        const int abase = (t & 31) << 2;                 // tabA index base
        const int bidx = ((t >> 4) & 31) | (r << 5);     // tabB index (fixed)

        float* fAX = (float*)sm->aX; float* fAY = (float*)sm->aY;
        float* fBX = (float*)sm->bX; float* fBY = (float*)sm->bY;
        float* csX = (float*)sm->cX; float* csY = (float*)sm->cY;

        // ---- analytic layer 0 (full layer incl wire 0 + perm + Phi_1) ----
        u64 AX[2], AY[2];
        {
            const float2* RU = sm->rawu;
            int x0 = t & 1, x1 = (t >> 1) & 1, x2 = (t >> 2) & 1, x3 = (t >> 3) & 1;
            int x4 = (t >> 4) & 1, x5 = (t >> 5) & 1, x6 = (t >> 6) & 1;
            int x7 = (t >> 7) & 1, x8 = (t >> 8) & 1;
            float2 P = RU[0 * 4 + r * 2 + b0];
            P = cmulf(P, RU[1 * 4 + (x8 ^ r) * 2 + b1]);
            P = cmulf(P, RU[2 * 4 + (x7 ^ x8) * 2]);
            P = cmulf(P, RU[3 * 4 + (x6 ^ x7) * 2]);
            P = cmulf(P, RU[4 * 4 + (x5 ^ x6) * 2]);
            P = cmulf(P, RU[5 * 4 + (x4 ^ x5) * 2]);
            P = cmulf(P, RU[6 * 4 + (x3 ^ x4) * 2]);
            P = cmulf(P, RU[7 * 4 + (x2 ^ x3) * 2]);
            P = cmulf(P, RU[8 * 4 + (x1 ^ x2) * 2]);
            P = cmulf(P, RU[9 * 4 + (x0 ^ x1) * 2]);
            P = cmulf(P, sm->tabB[0][bidx]);
            #pragma unroll
            for (int p = 0; p < 2; p++) {
                float2 Q  = cmulf(P, RU[10 * 4 + (p ^ x0) * 2]);   // m1 = p^t0
                float2 a0 = cmulf(Q, RU[11 * 4 + p * 2]);          // m0 = 0^p
                float2 a1 = cmulf(Q, RU[11 * 4 + (1 ^ p) * 2]);    // m0 = 1^p
                a0 = cmulf(a0, sm->tabA[0][abase | (p << 1)]);
                a1 = cmulf(a1, sm->tabA[0][abase | (p << 1) | 1]);
                AX[p] = pack2(a0.x, a1.x);
                AY[p] = pack2(a0.y, a1.y);
            }
        }

        #pragma unroll 1
        for (int l = 1; l < 8; l++) {
            const u64* CG = sm->coef + l * 12 * 4;
            // ---- real-RY gates on bits 0..6 (wires 11..5) ----
            gate_pck (AX, AY, CG + 11 * 4);
            gate_pair(AX, AY, CG + 10 * 4);
            gate_lane<1, 0>(AX, AY, CG + 9 * 4, t);
            gate_lane<2, 1>(AX, AY, CG + 8 * 4, t);
            gate_lane<4, 2>(AX, AY, CG + 7 * 4, t);
            gate_lane<8, 3>(AX, AY, CG + 6 * 4, t);
            gate_lane<16, 4>(AX, AY, CG + 5 * 4, t);
            // ---- transpose A: (lam,p) <-> (n9,n10) ----
            sm->aX[t] = AX[0]; sm->aX[512 + t] = AX[1];
            sm->aY[t] = AY[0]; sm->aY[512 + t] = AY[1];
            __syncthreads();
            #pragma unroll
            for (int p = 0; p < 2; p++) {
                int a = baseA ^ (p << 9);
                AX[p] = pack2(fAX[a], fAX[a ^ 256]);
                AY[p] = pack2(fAY[a], fAY[a ^ 256]);
            }
            gate_pck (AX, AY, CG + 2 * 4);
            gate_pair(AX, AY, CG + 1 * 4);
            // ---- transpose B: (lam,p) <-> (n7,n8) ----
            sm->bX[t] = AX[0]; sm->bX[512 + t] = AX[1];
            sm->bY[t] = AY[0]; sm->bY[512 + t] = AY[1];
            __syncthreads();
            #pragma unroll
            for (int p = 0; p < 2; p++) {
                int a = baseB ^ (p << 7);
                AX[p] = pack2(fBX[a], fBX[a ^ 64]);
                AY[p] = pack2(fBY[a], fBY[a ^ 64]);
            }
            gate_pck (AX, AY, CG + 4 * 4);
            gate_pair(AX, AY, CG + 3 * 4);
            // ---- exchange: wire-0 RY (branch r) x diag F_l, + CNOT perm ----
            u64* guX = g_sX[l & 1][col];
            u64* guY = g_sY[l & 1][col];
            const float* gfX = (const float*)guX;
            const float* gfY = (const float*)guY;
            stcg64(&guX[(r << 10) | t], AX[0]);
            stcg64(&guX[(r << 10) | 512 | t], AX[1]);
            stcg64(&guY[(r << 10) | t], AY[0]);
            stcg64(&guY[(r << 10) | 512 | t], AY[1]);
            sm->cX[t] = AX[0]; sm->cX[512 + t] = AX[1];
            sm->cY[t] = AY[0]; sm->cY[512 + t] = AY[1];
            __syncthreads();
            const uint32_t mb = (l & 1) ? mb1 : mb0;
            const unsigned par = (unsigned)(((l - 1) >> 1) & 1);
            if (t == 0) mbar_arrive_peer(mb, peer);
            // coefs + self terms in the arrive/wait shadow
            float2 Bf = sm->tabB[l][bidx];
            float2 r0 = sm->ry0[l];
            float c0 = r0.x;
            float co = r ? r0.y : -r0.y;
            u64 TX[2], TY[2], Oxp[2], Oyp[2], Onoyp[2];
            int a0s[2], a1s[2];
            #pragma unroll
            for (int p = 0; p < 2; p++) {
                float2 d0 = cmulf(sm->tabA[l][abase | (p << 1)], Bf);
                float2 d1 = cmulf(sm->tabA[l][abase | (p << 1) | 1], Bf);
                u64 sx  = pack2(d0.x * c0, d1.x * c0);
                u64 sy  = pack2(d0.y * c0, d1.y * c0);
                u64 nsy = pack2(-d0.y * c0, -d1.y * c0);
                Oxp[p]   = pack2(d0.x * co, d1.x * co);
                Oyp[p]   = pack2(d0.y * co, d1.y * co);
                Onoyp[p] = pack2(-d0.y * co, -d1.y * co);
                int a0 = gb ^ (p ? 768 : 0);
                int a1 = a0 ^ 256;
                a0s[p] = a0; a1s[p] = a1;
                u64 VX = pack2(csX[a0 & 2047], csX[a1 & 2047]);
                u64 VY = pack2(csY[a0 & 2047], csY[a1 & 2047]);
                TX[p] = fma2(nsy, VY, mul2(sx, VX));
                TY[p] = fma2(sy, VX, mul2(sx, VY));
            }
            mbar_wait(mb, par);
            #pragma unroll
            for (int p = 0; p < 2; p++) {
                int a0 = a0s[p] ^ 2048, a1 = a1s[p] ^ 2048;
                u64 PX = pack2(ldcg(gfX + a0), ldcg(gfX + a1));
                u64 PY = pack2(ldcg(gfY + a0), ldcg(gfY + a1));
                AX[p] = fma2(Onoyp[p], PY, fma2(Oxp[p], PX, TX[p]));
                AY[p] = fma2(Oyp[p], PX, fma2(Oxp[p], PY, TY[p]));
            }
        }

        // write column (natural order)
        #pragma unroll
        for (int p = 0; p < 2; p++) {
            float2 xs = unpack2(AX[p]), ys = unpack2(AY[p]);
            int n0 = (r << 11) | (((t >> 5) & 0xF) << 7) | ((t & 0x1F) << 2) | (p << 1);
            g_v[col][n0]     = make_float2(xs.x, ys.x);
            g_v[col][n0 | 1] = make_float2(xs.y, ys.y);
        }
        __syncthreads();
        if (t == 0) red_release_add(&g_flag, 1u);
        CLUSTER_ARRIVE();
        CLUSTER_WAIT();
    } else {
        // ================= OUTPUT BLOCK =================
        const int i = (bid - 8) * 512 + t;
        float s0 = 0.f, c0 = 1.f, s1 = 0.f, c1 = 1.f, hb = head_b[0];
        if (i < B) {
            float t0 = sb[i * 8 + 0], t1 = sb[i * 8 + 1];
            sincosf(t0 * 0.5f, &s0, &c0);
            sincosf(t1 * 0.5f, &s1, &c1);
        }
        float hw[12];
        #pragma unroll
        for (int w = 0; w < 12; w++) hw[w] = head_w[w];

        if (t == 0) {
            while (ld_acquire(&g_flag) < 8u) __nanosleep(32);
        }
        __syncthreads();

        // --- Gram: G[j][k] = sum_idx s(idx) v_j conj(v_k) ---
        float2 acc[4][4];
        #pragma unroll
        for (int a = 0; a < 4; a++)
            #pragma unroll
            for (int b = 0; b < 4; b++) acc[a][b] = make_float2(0.f, 0.f);

        for (int idx = t; idx < 4096; idx += 512) {
            float s = 0.f;
            #pragma unroll
            for (int w = 0; w < 12; w++)
                s += ((idx >> (11 - w)) & 1) ? -hw[w] : hw[w];
            float2 v[4];
            #pragma unroll
            for (int a = 0; a < 4; a++) v[a] = g_v[a][idx];
            #pragma unroll
            for (int a = 0; a < 4; a++)
                #pragma unroll
                for (int b = 0; b < 4; b++) {
                    float pr = v[a].x * v[b].x + v[a].y * v[b].y;
                    float pi = v[a].y * v[b].x - v[a].x * v[b].y;
                    acc[a][b].x += s * pr;
                    acc[a][b].y += s * pi;
                }
        }

        float* red = (float*)smem_raw;      // [16][32]
        float* Gs  = red + 16 * 32;         // [32]
        float* flat = reinterpret_cast<float*>(acc);
        const int lane = t & 31, warp = t >> 5;
        #pragma unroll
        for (int comp = 0; comp < 32; comp++) {
            float v = flat[comp];
            #pragma unroll
            for (int off = 16; off; off >>= 1)
                v += __shfl_down_sync(0xffffffff, v, off);
            if (lane == 0) red[warp * 32 + comp] = v;
        }
        __syncthreads();
        if (t < 32) {
            float v = 0.f;
            #pragma unroll
            for (int w = 0; w < 16; w++) v += red[w * 32 + t];
            Gs[t] = v;
        }
        __syncthreads();

        // self-resetting flags for graph replays
        if (t == 0) {
            int d = atomicAdd(&g_done2, 1);
            if (d == nOut - 1) {
                atomicExch(&g_flag, 0u);
                atomicExch(&g_done2, 0);
            }
        }

        // --- per-sample output: out = Re(c^H G c) + bias ---
        if (i < B) {
            float2 c[4];
            c[0] = make_float2(c0 * c1, 0.f);
            c[1] = make_float2(c0 * s1, 0.f);
            c[2] = make_float2(0.f, -s0 * c1);
            c[3] = make_float2(0.f, -s0 * s1);

            float res = hb;
            #pragma unroll
            for (int jj = 0; jj < 4; jj++)
                #pragma unroll
                for (int k = 0; k < 4; k++) {
                    float ccr = c[jj].x * c[k].x + c[jj].y * c[k].y;
                    float cci = c[jj].y * c[k].x - c[jj].x * c[k].y;
                    float gx = Gs[(jj * 4 + k) * 2];
                    float gy = Gs[(jj * 4 + k) * 2 + 1];
                    res += ccr * gx - cci * gy;
                }
            out[i] = res;
        }
    }
}

extern "C" void kernel_launch(void* const* d_in, const int* in_sizes, int n_in,
                              void* d_out, int out_size) {
    const float* state_batch = (const float*)d_in[0];  // (B, 8)
    const float* weights     = (const float*)d_in[1];  // (8, 12, 3)
    const float* head_w      = (const float*)d_in[2];  // (1, 12)
    const float* head_b      = (const float*)d_in[3];  // (1,)
    float* out = (float*)d_out;
    const int B = in_sizes[0] / 8;

    const int smem_bytes = (int)sizeof(SimSmem);
    cudaFuncSetAttribute(fused_kernel, cudaFuncAttributeMaxDynamicSharedMemorySize,
                         smem_bytes);
    int nOut = (B + 511) / 512;
    nOut += (nOut & 1);   // grid must be even for cluster_dims (2,1,1)
    fused_kernel<<<8 + nOut, 512, smem_bytes>>>(weights, head_w, head_b,
                                                state_batch, out, B, nOut);
}